// round 9
// baseline (speedup 1.0000x reference)
#include <cuda_runtime.h>
#include <math.h>
#include <stdint.h>

#define B_    4
#define N_    4096
#define FIN   128
#define FOUT  64
#define NROWS (B_ * N_)      // 16384
#define SPLIT 4
#define TILES_PER_SPLIT (64 / SPLIT)

// Scratch (__device__ globals; allocation-free rule)
__device__ float g_h   [NROWS * FOUT];          // tf32-rounded, [b][n][f]
__device__ float g_sself[NROWS];
__device__ float g_snei [NROWS];
__device__ float g_pC  [SPLIT * NROWS * FOUT];  // partial aggregations
__device__ float g_pl  [SPLIT * NROWS];         // partial exp-sums

__device__ __forceinline__ uint32_t tf32_rna(float x) {
    uint32_t u;
    asm("cvt.rna.tf32.f32 %0, %1;" : "=r"(u) : "f"(x));
    return u;
}
__device__ __forceinline__ uint32_t smem_u32(const void* p) {
    uint32_t a;
    asm("{ .reg .u64 t; cvta.to.shared.u64 t, %1; cvt.u32.u64 %0, t; }"
        : "=r"(a) : "l"(p));
    return a;
}
#define CP_ASYNC16(dst, src) \
    asm volatile("cp.async.ca.shared.global [%0], [%1], 16;" :: "r"(dst), "l"(src) : "memory")
#define CP_COMMIT()  asm volatile("cp.async.commit_group;" ::: "memory")
#define CP_WAIT0()   asm volatile("cp.async.wait_group 0;" ::: "memory")

// D(16x8,f32) += A(16x8,tf32,row) * B(8x8,tf32,col)
__device__ __forceinline__ void mma_tf32(float c[4], uint32_t a0, uint32_t a1,
                                         uint32_t a2, uint32_t a3,
                                         uint32_t b0, uint32_t b1) {
    asm volatile(
        "mma.sync.aligned.m16n8k8.row.col.f32.tf32.tf32.f32 "
        "{%0,%1,%2,%3}, {%4,%5,%6,%7}, {%8,%9}, {%0,%1,%2,%3};"
        : "+f"(c[0]), "+f"(c[1]), "+f"(c[2]), "+f"(c[3])
        : "r"(a0), "r"(a1), "r"(a2), "r"(a3), "r"(b0), "r"(b1));
}

// ---------------------------------------------------------------------------
// K1: h = x @ W; store tf32-rounded h; fp32 s_self, s_nei
// ---------------------------------------------------------------------------
__global__ void __launch_bounds__(64) gat_prep(const float* __restrict__ x,
                                               const float* __restrict__ W,
                                               const float* __restrict__ a) {
    const int r = blockIdx.x;
    const int f = threadIdx.x;
    __shared__ float xs[FIN];
    __shared__ float red[4];

    xs[f]      = x[(size_t)r * FIN + f];
    xs[f + 64] = x[(size_t)r * FIN + 64 + f];
    __syncthreads();

    float acc = 0.f;
#pragma unroll 16
    for (int k = 0; k < FIN; k++)
        acc = fmaf(xs[k], W[k * FOUT + f], acc);

    const float a1 = a[f];
    const float a2 = a[FOUT + f];

    g_h[(size_t)r * FOUT + f] = __uint_as_float(tf32_rna(acc));

    float v1 = acc * a1;
    float v2 = acc * a2;
#pragma unroll
    for (int mm = 16; mm; mm >>= 1) {
        v1 += __shfl_xor_sync(0xffffffffu, v1, mm);
        v2 += __shfl_xor_sync(0xffffffffu, v2, mm);
    }
    if ((f & 31) == 0) { red[f >> 5] = v1; red[2 + (f >> 5)] = v2; }
    __syncthreads();
    if (f == 0) {
        g_sself[r] = red[0] + red[1];
        g_snei [r] = red[2] + red[3];
    }
}

// ---------------------------------------------------------------------------
// K2: fused attention partial, mma.sync tf32. BM=64 rows/block (4 warps),
// BN=64 j per tile, TILES_PER_SPLIT tiles per block, split over blockIdx.z.
// Partials are exactly additive (no running-max softmax; scores bounded).
// smem (floats): HA3[64][68], HJ0/HJ1[64][68], PS 4x[16][68]  -> 68 KB
// ---------------------------------------------------------------------------
#define STR   68
#define F_HA3 0
#define F_HJ0 4352
#define F_HJ1 8704
#define F_PS  13056
#define SMEM_FLOATS 17408

__global__ void __launch_bounds__(128, 3)
gat_attn_mma(const int* __restrict__ adj, const float* __restrict__ a_vec) {
    extern __shared__ float sm[];
    const uint32_t sb = smem_u32(sm);

    const int tid  = threadIdx.x;
    const int lane = tid & 31, w = tid >> 5;
    const int g    = lane >> 2, tg = lane & 3;
    const int b    = blockIdx.y;
    const int i0   = blockIdx.x * 64;
    const int split = blockIdx.z;
    const int jbase = split * (TILES_PER_SPLIT * 64);
    const int row0 = 16 * w + g;        // local rows this thread owns
    const int row1 = row0 + 8;

    const float* hB    = g_h + (size_t)b * N_ * FOUT;
    const float* sneiB = g_snei + (size_t)b * N_;
    const int*   adjB  = adj + (size_t)b * N_ * N_;

    float* PSw = sm + F_PS + w * (16 * STR);

    // ---- prologue: build ha3 tile in smem from h * a3 (RNA->tf32) ----
    {
        const float4* hI = (const float4*)(hB + (size_t)i0 * FOUT);
        const float4* a3v = (const float4*)(a_vec + 2 * FOUT);
#pragma unroll
        for (int it = 0; it < 8; it++) {
            int idx = tid + it * 128;
            int rI = idx >> 4, q = idx & 15;
            float4 v = hI[idx];
            float4 s = __ldg(a3v + q);
            v.x = __uint_as_float(tf32_rna(v.x * s.x));
            v.y = __uint_as_float(tf32_rna(v.y * s.y));
            v.z = __uint_as_float(tf32_rna(v.z * s.z));
            v.w = __uint_as_float(tf32_rna(v.w * s.w));
            *(float4*)&sm[F_HA3 + rI * STR + 4 * q] = v;
        }
    }
    // ---- prologue: hj tile 0 of this split via cp.async ----
    {
        const char* src = (const char*)(hB + (size_t)jbase * FOUT);
#pragma unroll
        for (int it = 0; it < 8; it++) {
            int idx = tid + it * 128;
            int rI = idx >> 4, q = idx & 15;
            CP_ASYNC16(sb + (F_HJ0 + rI * STR + 4 * q) * 4, src + (size_t)idx * 16);
        }
    }
    CP_COMMIT();

    const float vself0 = g_sself[(size_t)b * N_ + i0 + row0];
    const float vself1 = g_sself[(size_t)b * N_ + i0 + row1];

    float l0 = 0.f, l1 = 0.f;
    float C2[8][4];
#pragma unroll
    for (int nt = 0; nt < 8; nt++)
#pragma unroll
        for (int c = 0; c < 4; c++) C2[nt][c] = 0.f;

    const size_t adjOff0 = (size_t)(i0 + row0) * N_;
    const size_t adjOff1 = (size_t)(i0 + row1) * N_;

    for (int tt = 0; tt < TILES_PER_SPLIT; tt++) {
        const int cb = tt & 1;
        const int j0 = jbase + (tt << 6);
        const float* hjc = sm + (cb ? F_HJ1 : F_HJ0);

        CP_WAIT0();
        __syncthreads();      // hj[cb] ready; prior tile reads done

        // ---- adj + snei prefetch (consumed in epilogue, hidden by GEMM1) ----
        int2 adv0[8], adv1[8];
        float2 snv[8];
        {
            const int2* p0 = (const int2*)(adjB + adjOff0 + j0);
            const int2* p1 = (const int2*)(adjB + adjOff1 + j0);
            const float2* ps = (const float2*)(sneiB + j0);
#pragma unroll
            for (int nt = 0; nt < 8; nt++) adv0[nt] = p0[4 * nt + tg];
#pragma unroll
            for (int nt = 0; nt < 8; nt++) adv1[nt] = p1[4 * nt + tg];
#pragma unroll
            for (int nt = 0; nt < 8; nt++) snv[nt] = __ldg(ps + 4 * nt + tg);
        }

        // ---- issue next hj tile loads (cp.async, other buffer) ----
        if (tt < TILES_PER_SPLIT - 1) {
            const int f_dst = cb ? F_HJ0 : F_HJ1;
            const char* src = (const char*)(hB + (size_t)(j0 + 64) * FOUT);
#pragma unroll
            for (int it = 0; it < 8; it++) {
                int idx = tid + it * 128;
                int rI = idx >> 4, q = idx & 15;
                CP_ASYNC16(sb + (f_dst + rI * STR + 4 * q) * 4, src + (size_t)idx * 16);
            }
        }
        CP_COMMIT();

        // ---- GEMM1: S[16x64] = ha3[16x64] @ hj[64x64]^T ----
        float S[8][4];
#pragma unroll
        for (int nt = 0; nt < 8; nt++)
#pragma unroll
            for (int c = 0; c < 4; c++) S[nt][c] = 0.f;

#pragma unroll
        for (int kc = 0; kc < 8; kc++) {
            const int k = 8 * kc + tg;
            const uint32_t a0 = __float_as_uint(sm[F_HA3 + row0 * STR + k]);
            const uint32_t a1 = __float_as_uint(sm[F_HA3 + row1 * STR + k]);
            const uint32_t a2 = __float_as_uint(sm[F_HA3 + row0 * STR + k + 4]);
            const uint32_t a3 = __float_as_uint(sm[F_HA3 + row1 * STR + k + 4]);
#pragma unroll
            for (int nt = 0; nt < 8; nt++) {
                const uint32_t b0 = __float_as_uint(hjc[(8 * nt + g) * STR + k]);
                const uint32_t b1 = __float_as_uint(hjc[(8 * nt + g) * STR + k + 4]);
                mma_tf32(S[nt], a0, a1, a2, a3, b0, b1);
            }
        }

        // ---- epilogue: scores -> lrelu -> mask -> exp -> P (tf32) ----
#pragma unroll
        for (int nt = 0; nt < 8; nt++) {
            const int col = 8 * nt + 2 * tg;
            const float sn0 = snv[nt].x;
            const float sn1 = snv[nt].y;
            float e, p00, p01, p10, p11;

            e = vself0 + sn0 + S[nt][0]; e = (e > 0.f) ? e : 0.2f * e;
            p00 = (adv0[nt].x > 0) ? __expf(e) : 0.f;
            e = vself0 + sn1 + S[nt][1]; e = (e > 0.f) ? e : 0.2f * e;
            p01 = (adv0[nt].y > 0) ? __expf(e) : 0.f;
            e = vself1 + sn0 + S[nt][2]; e = (e > 0.f) ? e : 0.2f * e;
            p10 = (adv1[nt].x > 0) ? __expf(e) : 0.f;
            e = vself1 + sn1 + S[nt][3]; e = (e > 0.f) ? e : 0.2f * e;
            p11 = (adv1[nt].y > 0) ? __expf(e) : 0.f;

            l0 += p00 + p01;
            l1 += p10 + p11;

            float2 v0, v1;
            v0.x = __uint_as_float(tf32_rna(p00));
            v0.y = __uint_as_float(tf32_rna(p01));
            v1.x = __uint_as_float(tf32_rna(p10));
            v1.y = __uint_as_float(tf32_rna(p11));
            *(float2*)&PSw[g * STR + col] = v0;
            *(float2*)&PSw[(g + 8) * STR + col] = v1;
        }
        __syncwarp();

        // ---- GEMM2: C2[16x64] += P[16x64] @ hj[64x64] ----
#pragma unroll
        for (int kc = 0; kc < 8; kc++) {
            const int k = 8 * kc + tg;
            const uint32_t a0 = __float_as_uint(PSw[g * STR + k]);
            const uint32_t a1 = __float_as_uint(PSw[(g + 8) * STR + k]);
            const uint32_t a2 = __float_as_uint(PSw[g * STR + k + 4]);
            const uint32_t a3 = __float_as_uint(PSw[(g + 8) * STR + k + 4]);
#pragma unroll
            for (int nt = 0; nt < 8; nt++) {
                const uint32_t b0 = __float_as_uint(hjc[k * STR + 8 * nt + g]);
                const uint32_t b1 = __float_as_uint(hjc[(k + 4) * STR + 8 * nt + g]);
                mma_tf32(C2[nt], a0, a1, a2, a3, b0, b1);
            }
        }
    }

    // ---- write partials: l (per row) and C (per row x 64) ----
    l0 += __shfl_xor_sync(0xffffffffu, l0, 1);
    l0 += __shfl_xor_sync(0xffffffffu, l0, 2);
    l1 += __shfl_xor_sync(0xffffffffu, l1, 1);
    l1 += __shfl_xor_sync(0xffffffffu, l1, 2);

    const size_t grow0 = (size_t)b * N_ + i0 + row0;
    const size_t grow1 = (size_t)b * N_ + i0 + row1;
    if (tg == 0) {
        g_pl[(size_t)split * NROWS + grow0] = l0;
        g_pl[(size_t)split * NROWS + grow1] = l1;
    }
    float* c0 = g_pC + ((size_t)split * NROWS + grow0) * FOUT;
    float* c1 = g_pC + ((size_t)split * NROWS + grow1) * FOUT;
#pragma unroll
    for (int nt = 0; nt < 8; nt++) {
        const int col = 8 * nt + 2 * tg;
        *(float2*)(c0 + col) = make_float2(C2[nt][0], C2[nt][1]);
        *(float2*)(c1 + col) = make_float2(C2[nt][2], C2[nt][3]);
    }
}

// ---------------------------------------------------------------------------
// K3: combine partials, normalize, ELU
// ---------------------------------------------------------------------------
__global__ void __launch_bounds__(256) gat_combine(float* __restrict__ out) {
    const int idx = blockIdx.x * 256 + threadIdx.x;   // 0 .. NROWS*16-1
    const int row = idx >> 4;
    const int q   = idx & 15;

    float l = 0.f;
#pragma unroll
    for (int s = 0; s < SPLIT; s++) l += g_pl[(size_t)s * NROWS + row];

    float4 c = make_float4(0.f, 0.f, 0.f, 0.f);
#pragma unroll
    for (int s = 0; s < SPLIT; s++) {
        const float4 v = ((const float4*)g_pC)[((size_t)s * NROWS + row) * 16 + q];
        c.x += v.x; c.y += v.y; c.z += v.z; c.w += v.w;
    }
    const float inv = 1.0f / l;
    float v; float4 o;
    v = c.x * inv; o.x = (v > 0.f) ? v : expm1f(v);
    v = c.y * inv; o.y = (v > 0.f) ? v : expm1f(v);
    v = c.z * inv; o.z = (v > 0.f) ? v : expm1f(v);
    v = c.w * inv; o.w = (v > 0.f) ? v : expm1f(v);
    ((float4*)out)[idx] = o;
}

// ---------------------------------------------------------------------------
extern "C" void kernel_launch(void* const* d_in, const int* in_sizes, int n_in,
                              void* d_out, int out_size) {
    const float* x   = (const float*)d_in[0];   // (4,4096,128) f32
    const int*   adj = (const int*)  d_in[1];   // (4,4096,4096) i32
    const float* W   = (const float*)d_in[2];   // (128,64) f32
    const float* a   = (const float*)d_in[3];   // (192,1) f32
    float* out = (float*)d_out;                 // (4,4096,64) f32

    gat_prep<<<NROWS, 64>>>(x, W, a);

    const int smem_bytes = SMEM_FLOATS * (int)sizeof(float);
    cudaFuncSetAttribute(gat_attn_mma,
                         cudaFuncAttributeMaxDynamicSharedMemorySize, smem_bytes);
    gat_attn_mma<<<dim3(N_ / 64, B_, SPLIT), 128, smem_bytes>>>(adj, a);

    gat_combine<<<(NROWS * 16) / 256, 256>>>(out);
}

// round 10
// speedup vs baseline: 1.0019x; 1.0019x over previous
#include <cuda_runtime.h>
#include <math.h>
#include <stdint.h>

#define B_    4
#define N_    4096
#define FIN   128
#define FOUT  64
#define NROWS (B_ * N_)      // 16384
#define SPLIT 4
#define TILES_PER_SPLIT (64 / SPLIT)

// Scratch (__device__ globals; allocation-free rule)
__device__ float g_h   [NROWS * FOUT];          // tf32-rounded, [b][n][f]
__device__ float g_sself[NROWS];
__device__ float g_snei [NROWS];
__device__ float g_pC  [SPLIT * NROWS * FOUT];  // partial aggregations
__device__ float g_pl  [SPLIT * NROWS];         // partial exp-sums

__device__ __forceinline__ uint32_t tf32_rna(float x) {
    uint32_t u;
    asm("cvt.rna.tf32.f32 %0, %1;" : "=r"(u) : "f"(x));
    return u;
}
__device__ __forceinline__ uint32_t smem_u32(const void* p) {
    uint32_t a;
    asm("{ .reg .u64 t; cvta.to.shared.u64 t, %1; cvt.u32.u64 %0, t; }"
        : "=r"(a) : "l"(p));
    return a;
}
#define CP_ASYNC16(dst, src) \
    asm volatile("cp.async.ca.shared.global [%0], [%1], 16;" :: "r"(dst), "l"(src) : "memory")
#define CP_COMMIT()  asm volatile("cp.async.commit_group;" ::: "memory")
#define CP_WAIT0()   asm volatile("cp.async.wait_group 0;" ::: "memory")

// D(16x8,f32) += A(16x8,tf32,row) * B(8x8,tf32,col)
__device__ __forceinline__ void mma_tf32(float c[4], uint32_t a0, uint32_t a1,
                                         uint32_t a2, uint32_t a3,
                                         uint32_t b0, uint32_t b1) {
    asm volatile(
        "mma.sync.aligned.m16n8k8.row.col.f32.tf32.tf32.f32 "
        "{%0,%1,%2,%3}, {%4,%5,%6,%7}, {%8,%9}, {%0,%1,%2,%3};"
        : "+f"(c[0]), "+f"(c[1]), "+f"(c[2]), "+f"(c[3])
        : "r"(a0), "r"(a1), "r"(a2), "r"(a3), "r"(b0), "r"(b1));
}

// ---------------------------------------------------------------------------
// K1: h = x @ W; store tf32-rounded h; fp32 s_self, s_nei
// ---------------------------------------------------------------------------
__global__ void __launch_bounds__(64) gat_prep(const float* __restrict__ x,
                                               const float* __restrict__ W,
                                               const float* __restrict__ a) {
    const int r = blockIdx.x;
    const int f = threadIdx.x;
    __shared__ float xs[FIN];
    __shared__ float red[4];

    xs[f]      = x[(size_t)r * FIN + f];
    xs[f + 64] = x[(size_t)r * FIN + 64 + f];
    __syncthreads();

    float acc = 0.f;
#pragma unroll 16
    for (int k = 0; k < FIN; k++)
        acc = fmaf(xs[k], W[k * FOUT + f], acc);

    const float a1 = a[f];
    const float a2 = a[FOUT + f];

    g_h[(size_t)r * FOUT + f] = __uint_as_float(tf32_rna(acc));

    float v1 = acc * a1;
    float v2 = acc * a2;
#pragma unroll
    for (int mm = 16; mm; mm >>= 1) {
        v1 += __shfl_xor_sync(0xffffffffu, v1, mm);
        v2 += __shfl_xor_sync(0xffffffffu, v2, mm);
    }
    if ((f & 31) == 0) { red[f >> 5] = v1; red[2 + (f >> 5)] = v2; }
    __syncthreads();
    if (f == 0) {
        g_sself[r] = red[0] + red[1];
        g_snei [r] = red[2] + red[3];
    }
}

// ---------------------------------------------------------------------------
// K2: fused attention partial, mma.sync tf32. BM=64 rows/block (4 warps),
// BN=64 j per tile, TILES_PER_SPLIT tiles per block, split over blockIdx.z.
// Partials are exactly additive (no running-max softmax; scores bounded).
// smem (floats): HA3[64][68], HJ0/HJ1[64][68], PS 4x[16][68]  -> 68 KB
// ---------------------------------------------------------------------------
#define STR   68
#define F_HA3 0
#define F_HJ0 4352
#define F_HJ1 8704
#define F_PS  13056
#define SMEM_FLOATS 17408

__global__ void __launch_bounds__(128, 3)
gat_attn_mma(const int* __restrict__ adj, const float* __restrict__ a_vec) {
    extern __shared__ float sm[];
    const uint32_t sb = smem_u32(sm);

    const int tid  = threadIdx.x;
    const int lane = tid & 31, w = tid >> 5;
    const int g    = lane >> 2, tg = lane & 3;
    const int b    = blockIdx.y;
    const int i0   = blockIdx.x * 64;
    const int split = blockIdx.z;
    const int jbase = split * (TILES_PER_SPLIT * 64);
    const int row0 = 16 * w + g;        // local rows this thread owns
    const int row1 = row0 + 8;

    const float* hB    = g_h + (size_t)b * N_ * FOUT;
    const float* sneiB = g_snei + (size_t)b * N_;
    const int*   adjB  = adj + (size_t)b * N_ * N_;

    float* PSw = sm + F_PS + w * (16 * STR);

    // ---- prologue: build ha3 tile in smem from h * a3 (RNA->tf32) ----
    {
        const float4* hI = (const float4*)(hB + (size_t)i0 * FOUT);
        const float4* a3v = (const float4*)(a_vec + 2 * FOUT);
#pragma unroll
        for (int it = 0; it < 8; it++) {
            int idx = tid + it * 128;
            int rI = idx >> 4, q = idx & 15;
            float4 v = hI[idx];
            float4 s = __ldg(a3v + q);
            v.x = __uint_as_float(tf32_rna(v.x * s.x));
            v.y = __uint_as_float(tf32_rna(v.y * s.y));
            v.z = __uint_as_float(tf32_rna(v.z * s.z));
            v.w = __uint_as_float(tf32_rna(v.w * s.w));
            *(float4*)&sm[F_HA3 + rI * STR + 4 * q] = v;
        }
    }
    // ---- prologue: hj tile 0 of this split via cp.async ----
    {
        const char* src = (const char*)(hB + (size_t)jbase * FOUT);
#pragma unroll
        for (int it = 0; it < 8; it++) {
            int idx = tid + it * 128;
            int rI = idx >> 4, q = idx & 15;
            CP_ASYNC16(sb + (F_HJ0 + rI * STR + 4 * q) * 4, src + (size_t)idx * 16);
        }
    }
    CP_COMMIT();

    const float vself0 = g_sself[(size_t)b * N_ + i0 + row0];
    const float vself1 = g_sself[(size_t)b * N_ + i0 + row1];

    float l0 = 0.f, l1 = 0.f;
    float C2[8][4];
#pragma unroll
    for (int nt = 0; nt < 8; nt++)
#pragma unroll
        for (int c = 0; c < 4; c++) C2[nt][c] = 0.f;

    const size_t adjOff0 = (size_t)(i0 + row0) * N_;
    const size_t adjOff1 = (size_t)(i0 + row1) * N_;

    for (int tt = 0; tt < TILES_PER_SPLIT; tt++) {
        const int cb = tt & 1;
        const int j0 = jbase + (tt << 6);
        const float* hjc = sm + (cb ? F_HJ1 : F_HJ0);

        CP_WAIT0();
        __syncthreads();      // hj[cb] ready; prior tile reads done

        // ---- adj + snei prefetch (consumed in epilogue, hidden by GEMM1) ----
        int2 adv0[8], adv1[8];
        float2 snv[8];
        {
            const int2* p0 = (const int2*)(adjB + adjOff0 + j0);
            const int2* p1 = (const int2*)(adjB + adjOff1 + j0);
            const float2* ps = (const float2*)(sneiB + j0);
#pragma unroll
            for (int nt = 0; nt < 8; nt++) adv0[nt] = p0[4 * nt + tg];
#pragma unroll
            for (int nt = 0; nt < 8; nt++) adv1[nt] = p1[4 * nt + tg];
#pragma unroll
            for (int nt = 0; nt < 8; nt++) snv[nt] = __ldg(ps + 4 * nt + tg);
        }

        // ---- issue next hj tile loads (cp.async, other buffer) ----
        if (tt < TILES_PER_SPLIT - 1) {
            const int f_dst = cb ? F_HJ0 : F_HJ1;
            const char* src = (const char*)(hB + (size_t)(j0 + 64) * FOUT);
#pragma unroll
            for (int it = 0; it < 8; it++) {
                int idx = tid + it * 128;
                int rI = idx >> 4, q = idx & 15;
                CP_ASYNC16(sb + (f_dst + rI * STR + 4 * q) * 4, src + (size_t)idx * 16);
            }
        }
        CP_COMMIT();

        // ---- GEMM1: S[16x64] = ha3[16x64] @ hj[64x64]^T ----
        float S[8][4];
#pragma unroll
        for (int nt = 0; nt < 8; nt++)
#pragma unroll
            for (int c = 0; c < 4; c++) S[nt][c] = 0.f;

#pragma unroll
        for (int kc = 0; kc < 8; kc++) {
            const int k = 8 * kc + tg;
            const uint32_t a0 = __float_as_uint(sm[F_HA3 + row0 * STR + k]);
            const uint32_t a1 = __float_as_uint(sm[F_HA3 + row1 * STR + k]);
            const uint32_t a2 = __float_as_uint(sm[F_HA3 + row0 * STR + k + 4]);
            const uint32_t a3 = __float_as_uint(sm[F_HA3 + row1 * STR + k + 4]);
#pragma unroll
            for (int nt = 0; nt < 8; nt++) {
                const uint32_t b0 = __float_as_uint(hjc[(8 * nt + g) * STR + k]);
                const uint32_t b1 = __float_as_uint(hjc[(8 * nt + g) * STR + k + 4]);
                mma_tf32(S[nt], a0, a1, a2, a3, b0, b1);
            }
        }

        // ---- epilogue: scores -> lrelu -> mask -> exp -> P (tf32) ----
#pragma unroll
        for (int nt = 0; nt < 8; nt++) {
            const int col = 8 * nt + 2 * tg;
            const float sn0 = snv[nt].x;
            const float sn1 = snv[nt].y;
            float e, p00, p01, p10, p11;

            e = vself0 + sn0 + S[nt][0]; e = (e > 0.f) ? e : 0.2f * e;
            p00 = (adv0[nt].x > 0) ? __expf(e) : 0.f;
            e = vself0 + sn1 + S[nt][1]; e = (e > 0.f) ? e : 0.2f * e;
            p01 = (adv0[nt].y > 0) ? __expf(e) : 0.f;
            e = vself1 + sn0 + S[nt][2]; e = (e > 0.f) ? e : 0.2f * e;
            p10 = (adv1[nt].x > 0) ? __expf(e) : 0.f;
            e = vself1 + sn1 + S[nt][3]; e = (e > 0.f) ? e : 0.2f * e;
            p11 = (adv1[nt].y > 0) ? __expf(e) : 0.f;

            l0 += p00 + p01;
            l1 += p10 + p11;

            float2 v0, v1;
            v0.x = __uint_as_float(tf32_rna(p00));
            v0.y = __uint_as_float(tf32_rna(p01));
            v1.x = __uint_as_float(tf32_rna(p10));
            v1.y = __uint_as_float(tf32_rna(p11));
            *(float2*)&PSw[g * STR + col] = v0;
            *(float2*)&PSw[(g + 8) * STR + col] = v1;
        }
        __syncwarp();

        // ---- GEMM2: C2[16x64] += P[16x64] @ hj[64x64] ----
#pragma unroll
        for (int kc = 0; kc < 8; kc++) {
            const int k = 8 * kc + tg;
            const uint32_t a0 = __float_as_uint(PSw[g * STR + k]);
            const uint32_t a1 = __float_as_uint(PSw[(g + 8) * STR + k]);
            const uint32_t a2 = __float_as_uint(PSw[g * STR + k + 4]);
            const uint32_t a3 = __float_as_uint(PSw[(g + 8) * STR + k + 4]);
#pragma unroll
            for (int nt = 0; nt < 8; nt++) {
                const uint32_t b0 = __float_as_uint(hjc[k * STR + 8 * nt + g]);
                const uint32_t b1 = __float_as_uint(hjc[(k + 4) * STR + 8 * nt + g]);
                mma_tf32(C2[nt], a0, a1, a2, a3, b0, b1);
            }
        }
    }

    // ---- write partials: l (per row) and C (per row x 64) ----
    l0 += __shfl_xor_sync(0xffffffffu, l0, 1);
    l0 += __shfl_xor_sync(0xffffffffu, l0, 2);
    l1 += __shfl_xor_sync(0xffffffffu, l1, 1);
    l1 += __shfl_xor_sync(0xffffffffu, l1, 2);

    const size_t grow0 = (size_t)b * N_ + i0 + row0;
    const size_t grow1 = (size_t)b * N_ + i0 + row1;
    if (tg == 0) {
        g_pl[(size_t)split * NROWS + grow0] = l0;
        g_pl[(size_t)split * NROWS + grow1] = l1;
    }
    float* c0 = g_pC + ((size_t)split * NROWS + grow0) * FOUT;
    float* c1 = g_pC + ((size_t)split * NROWS + grow1) * FOUT;
#pragma unroll
    for (int nt = 0; nt < 8; nt++) {
        const int col = 8 * nt + 2 * tg;
        *(float2*)(c0 + col) = make_float2(C2[nt][0], C2[nt][1]);
        *(float2*)(c1 + col) = make_float2(C2[nt][2], C2[nt][3]);
    }
}

// ---------------------------------------------------------------------------
// K3: combine partials, normalize, ELU
// ---------------------------------------------------------------------------
__global__ void __launch_bounds__(256) gat_combine(float* __restrict__ out) {
    const int idx = blockIdx.x * 256 + threadIdx.x;   // 0 .. NROWS*16-1
    const int row = idx >> 4;
    const int q   = idx & 15;

    float l = 0.f;
#pragma unroll
    for (int s = 0; s < SPLIT; s++) l += g_pl[(size_t)s * NROWS + row];

    float4 c = make_float4(0.f, 0.f, 0.f, 0.f);
#pragma unroll
    for (int s = 0; s < SPLIT; s++) {
        const float4 v = ((const float4*)g_pC)[((size_t)s * NROWS + row) * 16 + q];
        c.x += v.x; c.y += v.y; c.z += v.z; c.w += v.w;
    }
    const float inv = 1.0f / l;
    float v; float4 o;
    v = c.x * inv; o.x = (v > 0.f) ? v : expm1f(v);
    v = c.y * inv; o.y = (v > 0.f) ? v : expm1f(v);
    v = c.z * inv; o.z = (v > 0.f) ? v : expm1f(v);
    v = c.w * inv; o.w = (v > 0.f) ? v : expm1f(v);
    ((float4*)out)[idx] = o;
}

// ---------------------------------------------------------------------------
extern "C" void kernel_launch(void* const* d_in, const int* in_sizes, int n_in,
                              void* d_out, int out_size) {
    const float* x   = (const float*)d_in[0];   // (4,4096,128) f32
    const int*   adj = (const int*)  d_in[1];   // (4,4096,4096) i32
    const float* W   = (const float*)d_in[2];   // (128,64) f32
    const float* a   = (const float*)d_in[3];   // (192,1) f32
    float* out = (float*)d_out;                 // (4,4096,64) f32

    gat_prep<<<NROWS, 64>>>(x, W, a);

    const int smem_bytes = SMEM_FLOATS * (int)sizeof(float);
    cudaFuncSetAttribute(gat_attn_mma,
                         cudaFuncAttributeMaxDynamicSharedMemorySize, smem_bytes);
    gat_attn_mma<<<dim3(N_ / 64, B_, SPLIT), 128, smem_bytes>>>(adj, a);

    gat_combine<<<(NROWS * 16) / 256, 256>>>(out);
}